// round 1
// baseline (speedup 1.0000x reference)
#include <cuda_runtime.h>
#include <math.h>

// ---------------------------------------------------------------------------
// TreeModel: out = tree_probs(sigmoid(x@W_gate + b_gate)) @ leaf_logits
//   x           [16384, 1024] f32
//   W_gate      [1024, 1023]  f32 (row-major, ldb=1023)
//   b_gate      [1023]        f32
//   leaf_logits [1024, 1000]  f32 (row-major, ldb=1000)
//   out         [16384, 1000] f32
// DEPTH=11 -> 10 decision levels, 1023 inner nodes, 1024 leaves.
// ---------------------------------------------------------------------------

#define M_DIM 16384
#define K_DIM 1024
#define N_GATE 1023
#define N_OUT 1000

#define BM 128
#define BN 128
#define BK 8

// scratch (allocation-free): gate probabilities and leaf probabilities
__device__ float g_p[(size_t)M_DIM * 1024];      // sigmoid(x@W+b), padded to 1024 cols
__device__ float g_probs[(size_t)M_DIM * 1024];  // leaf probabilities

// ---------------------------------------------------------------------------
// Register-blocked SGEMM: C[M,N] = A[M,K] @ B[K,N]  (A row-major lda=K)
// EPI==1: C = sigmoid(A@B + bias)
// 256 threads, 128x128 block tile, 8x8 per-thread micro-tile, BK=8.
// M, K assumed multiples of BM/BK; N guarded (1023 / 1000).
// ---------------------------------------------------------------------------
template<int EPI>
__global__ __launch_bounds__(256, 2)
void sgemm_kernel(const float* __restrict__ A,
                  const float* __restrict__ B,
                  const float* __restrict__ bias,
                  float* __restrict__ C,
                  int N, int ldb, int ldc)
{
    __shared__ float As[BK][BM + 4];   // +4 pad: kill transpose-store conflicts
    __shared__ float Bs[BK][BN];

    const int t  = threadIdx.x;
    const int tx = t & 15;             // 0..15 (N direction)
    const int ty = t >> 4;             // 0..15 (M direction)
    const int bm0 = blockIdx.y * BM;
    const int bn0 = blockIdx.x * BN;

    // A tile loader: thread t loads float4 at (row = t>>1, kcol = (t&1)*4)
    const int arow = t >> 1;
    const int acol = (t & 1) * 4;
    const float* Aptr = A + (size_t)(bm0 + arow) * K_DIM + acol;

    // B tile loader: thread t loads 4 scalars at (kk = (t>>7)*4 + i, col = t&127)
    const int bcol = t & 127;
    const int bk0  = (t >> 7) * 4;
    const int gcol = bn0 + bcol;
    const bool bok = (gcol < N);

    float acc[8][8];
    #pragma unroll
    for (int i = 0; i < 8; i++)
        #pragma unroll
        for (int j = 0; j < 8; j++) acc[i][j] = 0.f;

    for (int k0 = 0; k0 < K_DIM; k0 += BK) {
        float4 av = *reinterpret_cast<const float4*>(Aptr + k0);
        As[acol + 0][arow] = av.x;
        As[acol + 1][arow] = av.y;
        As[acol + 2][arow] = av.z;
        As[acol + 3][arow] = av.w;
        #pragma unroll
        for (int i = 0; i < 4; i++) {
            int kk = bk0 + i;
            Bs[kk][bcol] = bok ? B[(size_t)(k0 + kk) * ldb + gcol] : 0.f;
        }
        __syncthreads();

        #pragma unroll
        for (int kk = 0; kk < BK; kk++) {
            float a[8], b[8];
            #pragma unroll
            for (int i = 0; i < 8; i++) a[i] = As[kk][ty * 8 + i];
            #pragma unroll
            for (int j = 0; j < 8; j++) b[j] = Bs[kk][tx * 8 + j];
            #pragma unroll
            for (int i = 0; i < 8; i++)
                #pragma unroll
                for (int j = 0; j < 8; j++)
                    acc[i][j] = fmaf(a[i], b[j], acc[i][j]);
        }
        __syncthreads();
    }

    // epilogue
    #pragma unroll
    for (int i = 0; i < 8; i++) {
        int row = bm0 + ty * 8 + i;
        #pragma unroll
        for (int j = 0; j < 8; j++) {
            int col = bn0 + tx * 8 + j;
            if (col < N) {
                float v = acc[i][j];
                if (EPI) {
                    v += bias[col];
                    v = 1.0f / (1.0f + __expf(-v));
                }
                C[(size_t)row * ldc + col] = v;
            }
        }
    }
}

// ---------------------------------------------------------------------------
// Tree path-product: probs[b, l] = prod_{k=0..9} gate(level k on path to l)
// Leaf l (10 bits, MSB = level-0 decision):
//   node(k)  = (1<<k)-1 + (l >> (10-k))
//   bit(k)   = (l >> (9-k)) & 1            (1 -> p, 0 -> 1-p)
// Block = 256 threads = 2 samples; each thread does 8 consecutive leaves,
// sharing the levels 0..6 prefix product (base = t*8 fixes the top 7 bits).
// ---------------------------------------------------------------------------
__global__ __launch_bounds__(256)
void tree_kernel()
{
    __shared__ float sp[2][1024];
    const int half = threadIdx.x >> 7;     // which sample in this block
    const int t    = threadIdx.x & 127;
    const int s    = blockIdx.x * 2 + half;

    const float* prow = g_p + (size_t)s * 1024;
    #pragma unroll
    for (int i = 0; i < 8; i++) {
        int idx = t + i * 128;
        if (idx < N_GATE) sp[half][idx] = prow[idx];
    }
    __syncthreads();

    const float* pr = sp[half];
    const int base = t * 8;

    // prefix over levels 0..6 (shared by the 8 leaves)
    float pref = 1.0f;
    #pragma unroll
    for (int k = 0; k < 7; k++) {
        int node = (1 << k) - 1 + (base >> (10 - k));
        int bit  = (base >> (9 - k)) & 1;
        float pv = pr[node];
        pref *= bit ? pv : (1.0f - pv);
    }

    // levels 7,8,9 fan out
    float p7 = pr[127 + (base >> 3)];
    float p8[2];
    p8[0] = pr[255 + (base >> 2) + 0];
    p8[1] = pr[255 + (base >> 2) + 1];
    float p9[4];
    #pragma unroll
    for (int i = 0; i < 4; i++) p9[i] = pr[511 + (base >> 1) + i];

    float o[8];
    #pragma unroll
    for (int j = 0; j < 8; j++) {
        int b2 = (j >> 2) & 1, b1 = (j >> 1) & 1, b0 = j & 1;
        float v = pref * (b2 ? p7 : (1.0f - p7));
        float q8 = p8[b2];
        v *= b1 ? q8 : (1.0f - q8);
        float q9 = p9[j >> 1];
        v *= b0 ? q9 : (1.0f - q9);
        o[j] = v;
    }

    float4* dst = reinterpret_cast<float4*>(g_probs + (size_t)s * 1024 + base);
    dst[0] = make_float4(o[0], o[1], o[2], o[3]);
    dst[1] = make_float4(o[4], o[5], o[6], o[7]);
}

// ---------------------------------------------------------------------------
extern "C" void kernel_launch(void* const* d_in, const int* in_sizes, int n_in,
                              void* d_out, int out_size)
{
    const float* x    = (const float*)d_in[0];
    const float* Wg   = (const float*)d_in[1];
    const float* bg   = (const float*)d_in[2];
    const float* leaf = (const float*)d_in[3];
    float* out = (float*)d_out;

    float* p_ptr = nullptr;
    float* probs_ptr = nullptr;
    cudaGetSymbolAddress((void**)&p_ptr, g_p);
    cudaGetSymbolAddress((void**)&probs_ptr, g_probs);

    // GEMM1 + sigmoid: g_p = sigmoid(x @ W_gate + b_gate), ldc padded to 1024
    {
        dim3 grid((N_GATE + BN - 1) / BN, M_DIM / BM);   // (8, 128)
        sgemm_kernel<1><<<grid, 256>>>(x, Wg, bg, p_ptr, N_GATE, N_GATE, 1024);
    }

    // tree product: g_probs from g_p
    tree_kernel<<<M_DIM / 2, 256>>>();

    // GEMM2: out = g_probs @ leaf_logits
    {
        dim3 grid((N_OUT + BN - 1) / BN, M_DIM / BM);    // (8, 128)
        sgemm_kernel<0><<<grid, 256>>>(probs_ptr, leaf, nullptr, out, N_OUT, N_OUT, N_OUT);
    }
}

// round 4
// speedup vs baseline: 3.3342x; 3.3342x over previous
#include <cuda_runtime.h>
#include <cuda_bf16.h>
#include <cstdint>

// ===========================================================================
// TreeModel via bf16x3-split HMMA (mma.sync) GEMMs — plain sm_100 compatible.
//   GEMM1: p = sigmoid(x @ W_gate + b)   [16384,1024]x[1024,1023]
//   tree : probs (path products)
//   GEMM2: out = probs @ leaf_logits     [16384,1024]x[1024,1000]
// fp32 = bf16_hi + bf16_lo; A@B ~= Ahi@Bhi + Ahi@Blo + Alo@Bhi (fp32 accum).
// ===========================================================================

#define M_DIM   16384
#define K_DIM   1024
#define N_GATE  1023
#define N_OUT   1000

#define BM      128
#define BN      128
#define BK      64          // 64 bf16 = 128B rows (swizzled)
#define NCHUNKS 48          // 3 passes * (1024 / 64)

#define A_BYTES (BM * BK * 2)        // 16 KB
#define B_BYTES (BN * BK * 2)        // 16 KB
#define STG_BYTES (A_BYTES + B_BYTES)
#define SMEM_TOTAL (2 * STG_BYTES)   // 64 KB, double buffered

// ---- scratch (static device allocations) ----
__device__ float          g_p   [(size_t)M_DIM * 1024];
__device__ __nv_bfloat16  g_xhi [(size_t)M_DIM * 1024];
__device__ __nv_bfloat16  g_xlo [(size_t)M_DIM * 1024];
__device__ __nv_bfloat16  g_phi [(size_t)M_DIM * 1024];
__device__ __nv_bfloat16  g_plo [(size_t)M_DIM * 1024];
__device__ __nv_bfloat16  g_whi [1024 * 1024];
__device__ __nv_bfloat16  g_wlo [1024 * 1024];
__device__ __nv_bfloat16  g_lhi [1024 * 1024];
__device__ __nv_bfloat16  g_llo [1024 * 1024];

__device__ __forceinline__ uint32_t smem_u32(const void* p) {
    uint32_t a;
    asm("{ .reg .u64 t; cvta.to.shared.u64 t, %1; cvt.u32.u64 %0, t; }" : "=r"(a) : "l"(p));
    return a;
}
__device__ __forceinline__ void cp16(uint32_t saddr, const void* gaddr) {
    asm volatile("cp.async.cg.shared.global [%0], [%1], 16;" :: "r"(saddr), "l"(gaddr));
}
__device__ __forceinline__ void ldsm_x4(uint32_t& r0, uint32_t& r1, uint32_t& r2, uint32_t& r3,
                                        uint32_t addr) {
    asm volatile("ldmatrix.sync.aligned.m8n8.x4.shared.b16 {%0,%1,%2,%3}, [%4];"
                 : "=r"(r0), "=r"(r1), "=r"(r2), "=r"(r3) : "r"(addr));
}
__device__ __forceinline__ void mma16816(float* c, const uint32_t* a, uint32_t b0, uint32_t b1) {
    asm volatile("mma.sync.aligned.m16n8k16.row.col.f32.bf16.bf16.f32 "
                 "{%0,%1,%2,%3}, {%4,%5,%6,%7}, {%8,%9}, {%0,%1,%2,%3};"
                 : "+f"(c[0]), "+f"(c[1]), "+f"(c[2]), "+f"(c[3])
                 : "r"(a[0]), "r"(a[1]), "r"(a[2]), "r"(a[3]), "r"(b0), "r"(b1));
}

// load one 128x64 A tile + 128x64 B tile into stage `st` (swizzled)
__device__ __forceinline__ void load_tiles(
    uint32_t sbase, int st, int tid, int bm0, int bn0, int k0,
    const __nv_bfloat16* __restrict__ A, const __nv_bfloat16* __restrict__ B)
{
    const uint32_t sa = sbase + (uint32_t)st * STG_BYTES;
    const uint32_t sb = sa + A_BYTES;
    #pragma unroll
    for (int i = 0; i < 4; i++) {
        int idx = i * 256 + tid;                 // 0..1023
        int row = idx >> 3;                      // 0..127
        int ch  = idx & 7;                       // 16B chunk in row
        uint32_t col = (uint32_t)ch * 16;
        uint32_t sw  = (uint32_t)row * 128 + (col ^ (((uint32_t)row & 7u) << 4));
        cp16(sa + sw, A + (size_t)(bm0 + row) * K_DIM + k0 + ch * 8);
        cp16(sb + sw, B + (size_t)(bn0 + row) * K_DIM + k0 + ch * 8);
    }
    asm volatile("cp.async.commit_group;" ::: "memory");
}

// ---------------------------------------------------------------------------
// EPI=1: sigmoid(acc + bias) -> C (ldc=1024)
// EPI=0: acc -> C (ldc=N_OUT, guard col < N_OUT)
// ---------------------------------------------------------------------------
template<int EPI>
__global__ void __launch_bounds__(256, 2)
hmma_gemm(const __nv_bfloat16* __restrict__ Ahi, const __nv_bfloat16* __restrict__ Alo,
          const __nv_bfloat16* __restrict__ Bhi, const __nv_bfloat16* __restrict__ Blo,
          const float* __restrict__ bias, float* __restrict__ C)
{
    extern __shared__ char smem[];
    const uint32_t sbase = smem_u32(smem);
    const int tid  = threadIdx.x;
    const int lane = tid & 31;
    const int wid  = tid >> 5;
    const int wm   = wid >> 1;          // 0..3
    const int wn   = wid & 1;           // 0..1
    const int m0w  = wm * 32;
    const int n0w  = wn * 64;
    const int bm0  = blockIdx.y * BM;
    const int bn0  = blockIdx.x * BN;

    // ldmatrix per-thread addressing:
    //   addr = rowBase + ((lh*16 + ks*32) ^ swmask)    (row bits disjoint from col bits)
    const int lr = lane & 15;
    const int lh = lane >> 4;
    uint32_t aRow[2], aSw[2], bRow[4], bSw[4];
    #pragma unroll
    for (int mt = 0; mt < 2; mt++) {
        int row = m0w + mt * 16 + lr;
        aRow[mt] = (uint32_t)row * 128;
        aSw[mt]  = ((uint32_t)row & 7u) << 4;
    }
    #pragma unroll
    for (int p = 0; p < 4; p++) {
        int row = n0w + p * 16 + lr;
        bRow[p] = (uint32_t)row * 128;
        bSw[p]  = ((uint32_t)row & 7u) << 4;
    }
    const uint32_t colBase = (uint32_t)lh * 16;

    float acc[2][8][4];
    #pragma unroll
    for (int mt = 0; mt < 2; mt++)
        #pragma unroll
        for (int nt = 0; nt < 8; nt++)
            #pragma unroll
            for (int q = 0; q < 4; q++) acc[mt][nt][q] = 0.f;

    // pass operand tables
    const __nv_bfloat16* Atab[3] = { Ahi, Ahi, Alo };
    const __nv_bfloat16* Btab[3] = { Bhi, Blo, Bhi };

    load_tiles(sbase, 0, tid, bm0, bn0, 0, Atab[0], Btab[0]);

    for (int c = 0; c < NCHUNKS; c++) {
        const int nc = c + 1;
        if (nc < NCHUNKS) {
            load_tiles(sbase, nc & 1, tid, bm0, bn0, (nc & 15) * BK,
                       Atab[nc >> 4], Btab[nc >> 4]);
            asm volatile("cp.async.wait_group 1;" ::: "memory");
        } else {
            asm volatile("cp.async.wait_group 0;" ::: "memory");
        }
        __syncthreads();

        const uint32_t sa = sbase + (uint32_t)(c & 1) * STG_BYTES;
        const uint32_t sb = sa + A_BYTES;

        #pragma unroll
        for (int ks = 0; ks < 4; ks++) {
            const uint32_t col = colBase + (uint32_t)ks * 32;
            uint32_t a[2][4];
            #pragma unroll
            for (int mt = 0; mt < 2; mt++)
                ldsm_x4(a[mt][0], a[mt][1], a[mt][2], a[mt][3],
                        sa + aRow[mt] + (col ^ aSw[mt]));
            uint32_t b[8][2];
            #pragma unroll
            for (int p = 0; p < 4; p++) {
                uint32_t r0, r1, r2, r3;
                ldsm_x4(r0, r1, r2, r3, sb + bRow[p] + (col ^ bSw[p]));
                b[p*2][0] = r0; b[p*2][1] = r2;
                b[p*2+1][0] = r1; b[p*2+1][1] = r3;
            }
            #pragma unroll
            for (int mt = 0; mt < 2; mt++)
                #pragma unroll
                for (int nt = 0; nt < 8; nt++)
                    mma16816(acc[mt][nt], a[mt], b[nt][0], b[nt][1]);
        }
        __syncthreads();   // all reads of this stage done before it is reloaded
    }

    // epilogue
    const int gq = lane >> 2;        // 0..7
    const int tq = lane & 3;         // 0..3
    #pragma unroll
    for (int mt = 0; mt < 2; mt++) {
        #pragma unroll
        for (int nt = 0; nt < 8; nt++) {
            const int col = bn0 + n0w + nt * 8 + tq * 2;
            const int r0  = bm0 + m0w + mt * 16 + gq;
            float v0 = acc[mt][nt][0], v1 = acc[mt][nt][1];
            float v2 = acc[mt][nt][2], v3 = acc[mt][nt][3];
            if (EPI == 1) {
                float b0 = (col     < N_GATE) ? bias[col]     : 0.f;
                float b1 = (col + 1 < N_GATE) ? bias[col + 1] : 0.f;
                v0 = 1.f / (1.f + __expf(-(v0 + b0)));
                v1 = 1.f / (1.f + __expf(-(v1 + b1)));
                v2 = 1.f / (1.f + __expf(-(v2 + b0)));
                v3 = 1.f / (1.f + __expf(-(v3 + b1)));
                *(float2*)(C + (size_t)r0 * 1024 + col)       = make_float2(v0, v1);
                *(float2*)(C + (size_t)(r0 + 8) * 1024 + col) = make_float2(v2, v3);
            } else {
                if (col + 1 < N_OUT) {
                    *(float2*)(C + (size_t)r0 * N_OUT + col)       = make_float2(v0, v1);
                    *(float2*)(C + (size_t)(r0 + 8) * N_OUT + col) = make_float2(v2, v3);
                } else if (col < N_OUT) {
                    C[(size_t)r0 * N_OUT + col]       = v0;
                    C[(size_t)(r0 + 8) * N_OUT + col] = v2;
                }
            }
        }
    }
}

// ---------------------------------------------------------------------------
// split: f32 -> bf16 hi + bf16 lo
// ---------------------------------------------------------------------------
__global__ void __launch_bounds__(256)
split_kernel(const float* __restrict__ in, __nv_bfloat16* __restrict__ hi,
             __nv_bfloat16* __restrict__ lo, int n4)
{
    int i = blockIdx.x * 256 + threadIdx.x;
    if (i >= n4) return;
    float4 v = ((const float4*)in)[i];
    __nv_bfloat16 h0 = __float2bfloat16(v.x), h1 = __float2bfloat16(v.y);
    __nv_bfloat16 h2 = __float2bfloat16(v.z), h3 = __float2bfloat16(v.w);
    __nv_bfloat162* H = (__nv_bfloat162*)hi;
    __nv_bfloat162* L = (__nv_bfloat162*)lo;
    H[i*2]   = __nv_bfloat162(h0, h1);
    H[i*2+1] = __nv_bfloat162(h2, h3);
    L[i*2]   = __nv_bfloat162(__float2bfloat16(v.x - __bfloat162float(h0)),
                              __float2bfloat16(v.y - __bfloat162float(h1)));
    L[i*2+1] = __nv_bfloat162(__float2bfloat16(v.z - __bfloat162float(h2)),
                              __float2bfloat16(v.w - __bfloat162float(h3)));
}

// ---------------------------------------------------------------------------
// transpose + split: in[1024, Nin] f32 -> hi/lo [1024(N, zero pad), 1024(K)]
// ---------------------------------------------------------------------------
__global__ void __launch_bounds__(256)
transpose_split_kernel(const float* __restrict__ in, int Nin,
                       __nv_bfloat16* __restrict__ hi, __nv_bfloat16* __restrict__ lo)
{
    __shared__ float t[32][33];
    const int k0 = blockIdx.x * 32, n0 = blockIdx.y * 32;
    const int x = threadIdx.x & 31, y = threadIdx.x >> 5;
    #pragma unroll
    for (int i = 0; i < 32; i += 8) {
        int n = n0 + x;
        t[y + i][x] = (n < Nin) ? in[(size_t)(k0 + y + i) * Nin + n] : 0.f;
    }
    __syncthreads();
    #pragma unroll
    for (int i = 0; i < 32; i += 8) {
        int n = n0 + y + i, k = k0 + x;
        float v = t[x][y + i];
        __nv_bfloat16 h = __float2bfloat16(v);
        hi[(size_t)n * 1024 + k] = h;
        lo[(size_t)n * 1024 + k] = __float2bfloat16(v - __bfloat162float(h));
    }
}

// ---------------------------------------------------------------------------
// Tree path-product -> probs as bf16 hi/lo.
// ---------------------------------------------------------------------------
__global__ void __launch_bounds__(256)
tree_kernel()
{
    __shared__ float sp[2][1024];
    const int half = threadIdx.x >> 7;
    const int t    = threadIdx.x & 127;
    const int s    = blockIdx.x * 2 + half;

    const float* prow = g_p + (size_t)s * 1024;
    #pragma unroll
    for (int i = 0; i < 8; i++) {
        int idx = t + i * 128;
        if (idx < N_GATE) sp[half][idx] = prow[idx];
    }
    __syncthreads();

    const float* pr = sp[half];
    const int base = t * 8;

    float pref = 1.0f;
    #pragma unroll
    for (int k = 0; k < 7; k++) {
        int node = (1 << k) - 1 + (base >> (10 - k));
        int bit  = (base >> (9 - k)) & 1;
        float pv = pr[node];
        pref *= bit ? pv : (1.0f - pv);
    }
    float p7 = pr[127 + (base >> 3)];
    float p8[2];
    p8[0] = pr[255 + (base >> 2) + 0];
    p8[1] = pr[255 + (base >> 2) + 1];
    float p9[4];
    #pragma unroll
    for (int i = 0; i < 4; i++) p9[i] = pr[511 + (base >> 1) + i];

    __align__(16) __nv_bfloat16 H[8];
    __align__(16) __nv_bfloat16 L[8];
    #pragma unroll
    for (int j = 0; j < 8; j++) {
        int b2 = (j >> 2) & 1, b1 = (j >> 1) & 1, b0 = j & 1;
        float v = pref * (b2 ? p7 : (1.0f - p7));
        float q8 = p8[b2];
        v *= b1 ? q8 : (1.0f - q8);
        float q9 = p9[j >> 1];
        v *= b0 ? q9 : (1.0f - q9);
        __nv_bfloat16 h = __float2bfloat16(v);
        H[j] = h;
        L[j] = __float2bfloat16(v - __bfloat162float(h));
    }
    *(uint4*)(g_phi + (size_t)s * 1024 + base) = *(uint4*)H;
    *(uint4*)(g_plo + (size_t)s * 1024 + base) = *(uint4*)L;
}

// ---------------------------------------------------------------------------
extern "C" void kernel_launch(void* const* d_in, const int* in_sizes, int n_in,
                              void* d_out, int out_size)
{
    const float* x    = (const float*)d_in[0];
    const float* Wg   = (const float*)d_in[1];
    const float* bg   = (const float*)d_in[2];
    const float* leaf = (const float*)d_in[3];
    float* out = (float*)d_out;

    float *p_ptr;
    __nv_bfloat16 *xhi, *xlo, *phi, *plo, *whi, *wlo, *lhi, *llo;
    cudaGetSymbolAddress((void**)&p_ptr, g_p);
    cudaGetSymbolAddress((void**)&xhi, g_xhi);
    cudaGetSymbolAddress((void**)&xlo, g_xlo);
    cudaGetSymbolAddress((void**)&phi, g_phi);
    cudaGetSymbolAddress((void**)&plo, g_plo);
    cudaGetSymbolAddress((void**)&whi, g_whi);
    cudaGetSymbolAddress((void**)&wlo, g_wlo);
    cudaGetSymbolAddress((void**)&lhi, g_lhi);
    cudaGetSymbolAddress((void**)&llo, g_llo);

    cudaFuncSetAttribute(hmma_gemm<1>, cudaFuncAttributeMaxDynamicSharedMemorySize, SMEM_TOTAL);
    cudaFuncSetAttribute(hmma_gemm<0>, cudaFuncAttributeMaxDynamicSharedMemorySize, SMEM_TOTAL);

    // prep: split x; transpose+split weights
    {
        int n4 = (M_DIM * K_DIM) / 4;
        split_kernel<<<(n4 + 255) / 256, 256>>>(x, xhi, xlo, n4);
        dim3 tg(32, 32);
        transpose_split_kernel<<<tg, 256>>>(Wg, N_GATE, whi, wlo);
        transpose_split_kernel<<<tg, 256>>>(leaf, N_OUT, lhi, llo);
    }

    // GEMM1 + sigmoid -> g_p
    {
        dim3 grid(1024 / BN, M_DIM / BM);   // (8, 128)
        hmma_gemm<1><<<grid, 256, SMEM_TOTAL>>>(xhi, xlo, whi, wlo, bg, p_ptr);
    }

    // tree products -> probs hi/lo
    tree_kernel<<<M_DIM / 2, 256>>>();

    // GEMM2 -> out
    {
        dim3 grid(1024 / BN, M_DIM / BM);   // (8, 128)
        hmma_gemm<0><<<grid, 256, SMEM_TOTAL>>>(phi, plo, lhi, llo, nullptr, out);
    }
}

// round 5
// speedup vs baseline: 4.6537x; 1.3958x over previous
#include <cuda_runtime.h>
#include <cuda_fp16.h>
#include <cstdint>

// ===========================================================================
// TreeModel via fp16 asymmetric-split HMMA GEMMs (2 passes).
//   GEMM1: p = sigmoid(x @ W_gate + b)   A = fp16(x),   B = Whi + Wlo
//   tree : probs (path products)         -> fp16
//   GEMM2: out = probs @ leaf_logits     A = fp16(probs), B = Lhi + Llo
// D = A@Bhi + A@Blo (fp32 accum). Dropped term = A rounding, ~2^-11 rel.
// ===========================================================================

#define M_DIM   16384
#define K_DIM   1024
#define N_GATE  1023
#define N_OUT   1000

#define BM      128
#define BN      128
#define BK      64          // 64 fp16 = 128B rows (swizzled)
#define NCHUNKS 32          // 2 passes * (1024 / 64)
#define STAGES  3

#define A_BYTES (BM * BK * 2)        // 16 KB
#define B_BYTES (BN * BK * 2)        // 16 KB
#define STG_BYTES (A_BYTES + B_BYTES)
#define SMEM_TOTAL (STAGES * STG_BYTES)   // 96 KB

// ---- scratch (static device allocations) ----
__device__ float   g_p  [(size_t)M_DIM * 1024];   // gate probabilities (f32)
__device__ __half  g_xh [(size_t)M_DIM * 1024];   // fp16(x)
__device__ __half  g_ph [(size_t)M_DIM * 1024];   // fp16(probs)
__device__ __half  g_wh [1024 * 1024];            // W_gate^T hi
__device__ __half  g_wl [1024 * 1024];            // W_gate^T lo
__device__ __half  g_lh [1024 * 1024];            // leaf^T hi
__device__ __half  g_ll [1024 * 1024];            // leaf^T lo

__device__ __forceinline__ uint32_t smem_u32(const void* p) {
    uint32_t a;
    asm("{ .reg .u64 t; cvta.to.shared.u64 t, %1; cvt.u32.u64 %0, t; }" : "=r"(a) : "l"(p));
    return a;
}
__device__ __forceinline__ void cp16(uint32_t saddr, const void* gaddr) {
    asm volatile("cp.async.cg.shared.global [%0], [%1], 16;" :: "r"(saddr), "l"(gaddr));
}
__device__ __forceinline__ void ldsm_x4(uint32_t& r0, uint32_t& r1, uint32_t& r2, uint32_t& r3,
                                        uint32_t addr) {
    asm volatile("ldmatrix.sync.aligned.m8n8.x4.shared.b16 {%0,%1,%2,%3}, [%4];"
                 : "=r"(r0), "=r"(r1), "=r"(r2), "=r"(r3) : "r"(addr));
}
__device__ __forceinline__ void mma16816(float* c, const uint32_t* a, uint32_t b0, uint32_t b1) {
    asm volatile("mma.sync.aligned.m16n8k16.row.col.f32.f16.f16.f32 "
                 "{%0,%1,%2,%3}, {%4,%5,%6,%7}, {%8,%9}, {%0,%1,%2,%3};"
                 : "+f"(c[0]), "+f"(c[1]), "+f"(c[2]), "+f"(c[3])
                 : "r"(a[0]), "r"(a[1]), "r"(a[2]), "r"(a[3]), "r"(b0), "r"(b1));
}

// load one 128x64 A tile + 128x64 B tile into stage `st` (swizzled)
__device__ __forceinline__ void load_tiles(
    uint32_t sbase, int st, int tid, int bm0, int bn0, int k0,
    const __half* __restrict__ A, const __half* __restrict__ B)
{
    const uint32_t sa = sbase + (uint32_t)st * STG_BYTES;
    const uint32_t sb = sa + A_BYTES;
    #pragma unroll
    for (int i = 0; i < 4; i++) {
        int idx = i * 256 + tid;                 // 0..1023
        int row = idx >> 3;                      // 0..127
        int ch  = idx & 7;                       // 16B chunk in row
        uint32_t col = (uint32_t)ch * 16;
        uint32_t sw  = (uint32_t)row * 128 + (col ^ (((uint32_t)row & 7u) << 4));
        cp16(sa + sw, A + (size_t)(bm0 + row) * K_DIM + k0 + ch * 8);
        cp16(sb + sw, B + (size_t)(bn0 + row) * K_DIM + k0 + ch * 8);
    }
    asm volatile("cp.async.commit_group;" ::: "memory");
}

// ---------------------------------------------------------------------------
// EPI=1: sigmoid(acc + bias) -> C (ldc=1024)
// EPI=0: acc -> C (ldc=N_OUT, guard col < N_OUT)
// ---------------------------------------------------------------------------
template<int EPI>
__global__ void __launch_bounds__(256, 2)
hmma_gemm(const __half* __restrict__ A,
          const __half* __restrict__ Bhi, const __half* __restrict__ Blo,
          const float* __restrict__ bias, float* __restrict__ C)
{
    extern __shared__ char smem[];
    const uint32_t sbase = smem_u32(smem);
    const int tid  = threadIdx.x;
    const int lane = tid & 31;
    const int wid  = tid >> 5;
    const int wm   = wid >> 1;          // 0..3
    const int wn   = wid & 1;           // 0..1
    const int m0w  = wm * 32;
    const int n0w  = wn * 64;
    const int bm0  = blockIdx.y * BM;
    const int bn0  = blockIdx.x * BN;

    // ldmatrix addressing: addr = rowBase + ((lh*16 + ks*32) ^ swmask)
    const int lr = lane & 15;
    const int lh = lane >> 4;
    const uint32_t sw = ((uint32_t)lr & 7u) << 4;   // row&7 == lr&7 for all tiles here
    uint32_t colX[4];
    #pragma unroll
    for (int ks = 0; ks < 4; ks++)
        colX[ks] = (((uint32_t)lh * 16) + (uint32_t)ks * 32) ^ sw;
    uint32_t aRow[2], bRow[4];
    #pragma unroll
    for (int mt = 0; mt < 2; mt++) aRow[mt] = (uint32_t)(m0w + mt * 16 + lr) * 128;
    #pragma unroll
    for (int p = 0; p < 4; p++)    bRow[p]  = (uint32_t)(n0w + p * 16 + lr) * 128;

    float acc[2][8][4];
    #pragma unroll
    for (int mt = 0; mt < 2; mt++)
        #pragma unroll
        for (int nt = 0; nt < 8; nt++)
            #pragma unroll
            for (int q = 0; q < 4; q++) acc[mt][nt][q] = 0.f;

    const __half* Btab[2] = { Bhi, Blo };

    load_tiles(sbase, 0, tid, bm0, bn0, 0, A, Btab[0]);
    load_tiles(sbase, 1, tid, bm0, bn0, BK, A, Btab[0]);

    for (int c = 0; c < NCHUNKS; c++) {
        if (c + 1 < NCHUNKS) asm volatile("cp.async.wait_group 1;" ::: "memory");
        else                 asm volatile("cp.async.wait_group 0;" ::: "memory");
        __syncthreads();   // stage c visible to all; compute c-1 done by all

        const int pc = c + 2;
        if (pc < NCHUNKS)
            load_tiles(sbase, pc % STAGES, tid, bm0, bn0, (pc & 15) * BK,
                       A, Btab[pc >> 4]);

        const uint32_t sa = sbase + (uint32_t)(c % STAGES) * STG_BYTES;
        const uint32_t sb = sa + A_BYTES;

        #pragma unroll
        for (int ks = 0; ks < 4; ks++) {
            uint32_t a[2][4];
            #pragma unroll
            for (int mt = 0; mt < 2; mt++)
                ldsm_x4(a[mt][0], a[mt][1], a[mt][2], a[mt][3], sa + aRow[mt] + colX[ks]);
            uint32_t b[8][2];
            #pragma unroll
            for (int p = 0; p < 4; p++) {
                uint32_t r0, r1, r2, r3;
                ldsm_x4(r0, r1, r2, r3, sb + bRow[p] + colX[ks]);
                b[p*2][0] = r0; b[p*2][1] = r2;
                b[p*2+1][0] = r1; b[p*2+1][1] = r3;
            }
            #pragma unroll
            for (int mt = 0; mt < 2; mt++)
                #pragma unroll
                for (int nt = 0; nt < 8; nt++)
                    mma16816(acc[mt][nt], a[mt], b[nt][0], b[nt][1]);
        }
    }

    // epilogue
    const int gq = lane >> 2;
    const int tq = lane & 3;
    #pragma unroll
    for (int mt = 0; mt < 2; mt++) {
        #pragma unroll
        for (int nt = 0; nt < 8; nt++) {
            const int col = bn0 + n0w + nt * 8 + tq * 2;
            const int r0  = bm0 + m0w + mt * 16 + gq;
            float v0 = acc[mt][nt][0], v1 = acc[mt][nt][1];
            float v2 = acc[mt][nt][2], v3 = acc[mt][nt][3];
            if (EPI == 1) {
                float b0 = (col     < N_GATE) ? bias[col]     : 0.f;
                float b1 = (col + 1 < N_GATE) ? bias[col + 1] : 0.f;
                v0 = 1.f / (1.f + __expf(-(v0 + b0)));
                v1 = 1.f / (1.f + __expf(-(v1 + b1)));
                v2 = 1.f / (1.f + __expf(-(v2 + b0)));
                v3 = 1.f / (1.f + __expf(-(v3 + b1)));
                *(float2*)(C + (size_t)r0 * 1024 + col)       = make_float2(v0, v1);
                *(float2*)(C + (size_t)(r0 + 8) * 1024 + col) = make_float2(v2, v3);
            } else {
                if (col + 1 < N_OUT) {
                    *(float2*)(C + (size_t)r0 * N_OUT + col)       = make_float2(v0, v1);
                    *(float2*)(C + (size_t)(r0 + 8) * N_OUT + col) = make_float2(v2, v3);
                } else if (col < N_OUT) {
                    C[(size_t)r0 * N_OUT + col]       = v0;
                    C[(size_t)(r0 + 8) * N_OUT + col] = v2;
                }
            }
        }
    }
}

// ---------------------------------------------------------------------------
// x: f32 -> fp16 (single)
// ---------------------------------------------------------------------------
__global__ void __launch_bounds__(256)
cvt_kernel(const float* __restrict__ in, __half* __restrict__ out, int n4)
{
    int i = blockIdx.x * 256 + threadIdx.x;
    if (i >= n4) return;
    float4 v = ((const float4*)in)[i];
    __half2* O = (__half2*)out;
    O[i*2]   = __floats2half2_rn(v.x, v.y);
    O[i*2+1] = __floats2half2_rn(v.z, v.w);
}

// ---------------------------------------------------------------------------
// transpose + split: in[1024, Nin] f32 -> hi/lo [1024(N, zero pad), 1024(K)] fp16
// ---------------------------------------------------------------------------
__global__ void __launch_bounds__(256)
transpose_split_kernel(const float* __restrict__ in, int Nin,
                       __half* __restrict__ hi, __half* __restrict__ lo)
{
    __shared__ float t[32][33];
    const int k0 = blockIdx.x * 32, n0 = blockIdx.y * 32;
    const int x = threadIdx.x & 31, y = threadIdx.x >> 5;
    #pragma unroll
    for (int i = 0; i < 32; i += 8) {
        int n = n0 + x;
        t[y + i][x] = (n < Nin) ? in[(size_t)(k0 + y + i) * Nin + n] : 0.f;
    }
    __syncthreads();
    #pragma unroll
    for (int i = 0; i < 32; i += 8) {
        int n = n0 + y + i, k = k0 + x;
        float v = t[x][y + i];
        __half h = __float2half_rn(v);
        hi[(size_t)n * 1024 + k] = h;
        lo[(size_t)n * 1024 + k] = __float2half_rn(v - __half2float(h));
    }
}

// ---------------------------------------------------------------------------
// Tree path-product -> probs as fp16.
// ---------------------------------------------------------------------------
__global__ void __launch_bounds__(256)
tree_kernel()
{
    __shared__ float sp[2][1024];
    const int half = threadIdx.x >> 7;
    const int t    = threadIdx.x & 127;
    const int s    = blockIdx.x * 2 + half;

    const float* prow = g_p + (size_t)s * 1024;
    #pragma unroll
    for (int i = 0; i < 8; i++) {
        int idx = t + i * 128;
        if (idx < N_GATE) sp[half][idx] = prow[idx];
    }
    __syncthreads();

    const float* pr = sp[half];
    const int base = t * 8;

    float pref = 1.0f;
    #pragma unroll
    for (int k = 0; k < 7; k++) {
        int node = (1 << k) - 1 + (base >> (10 - k));
        int bit  = (base >> (9 - k)) & 1;
        float pv = pr[node];
        pref *= bit ? pv : (1.0f - pv);
    }
    float p7 = pr[127 + (base >> 3)];
    float p8[2];
    p8[0] = pr[255 + (base >> 2) + 0];
    p8[1] = pr[255 + (base >> 2) + 1];
    float p9[4];
    #pragma unroll
    for (int i = 0; i < 4; i++) p9[i] = pr[511 + (base >> 1) + i];

    __align__(16) __half H[8];
    #pragma unroll
    for (int j = 0; j < 8; j++) {
        int b2 = (j >> 2) & 1, b1 = (j >> 1) & 1, b0 = j & 1;
        float v = pref * (b2 ? p7 : (1.0f - p7));
        float q8 = p8[b2];
        v *= b1 ? q8 : (1.0f - q8);
        float q9 = p9[j >> 1];
        v *= b0 ? q9 : (1.0f - q9);
        H[j] = __float2half_rn(v);
    }
    *(uint4*)(g_ph + (size_t)s * 1024 + base) = *(uint4*)H;
}

// ---------------------------------------------------------------------------
extern "C" void kernel_launch(void* const* d_in, const int* in_sizes, int n_in,
                              void* d_out, int out_size)
{
    const float* x    = (const float*)d_in[0];
    const float* Wg   = (const float*)d_in[1];
    const float* bg   = (const float*)d_in[2];
    const float* leaf = (const float*)d_in[3];
    float* out = (float*)d_out;

    float *p_ptr;
    __half *xh, *ph, *wh, *wl, *lh, *ll;
    cudaGetSymbolAddress((void**)&p_ptr, g_p);
    cudaGetSymbolAddress((void**)&xh, g_xh);
    cudaGetSymbolAddress((void**)&ph, g_ph);
    cudaGetSymbolAddress((void**)&wh, g_wh);
    cudaGetSymbolAddress((void**)&wl, g_wl);
    cudaGetSymbolAddress((void**)&lh, g_lh);
    cudaGetSymbolAddress((void**)&ll, g_ll);

    cudaFuncSetAttribute(hmma_gemm<1>, cudaFuncAttributeMaxDynamicSharedMemorySize, SMEM_TOTAL);
    cudaFuncSetAttribute(hmma_gemm<0>, cudaFuncAttributeMaxDynamicSharedMemorySize, SMEM_TOTAL);

    // prep: convert x; transpose+split weights
    {
        int n4 = (M_DIM * K_DIM) / 4;
        cvt_kernel<<<(n4 + 255) / 256, 256>>>(x, xh, n4);
        dim3 tg(32, 32);
        transpose_split_kernel<<<tg, 256>>>(Wg, N_GATE, wh, wl);
        transpose_split_kernel<<<tg, 256>>>(leaf, N_OUT, lh, ll);
    }

    // GEMM1 + sigmoid -> g_p
    {
        dim3 grid(1024 / BN, M_DIM / BM);   // (8, 128)
        hmma_gemm<1><<<grid, 256, SMEM_TOTAL>>>(xh, wh, wl, bg, p_ptr);
    }

    // tree products -> probs fp16
    tree_kernel<<<M_DIM / 2, 256>>>();

    // GEMM2 -> out
    {
        dim3 grid(1024 / BN, M_DIM / BM);   // (8, 128)
        hmma_gemm<0><<<grid, 256, SMEM_TOTAL>>>(ph, lh, ll, nullptr, out);
    }
}

// round 6
// speedup vs baseline: 7.9812x; 1.7150x over previous
#include <cuda_runtime.h>
#include <cuda_fp16.h>
#include <cstdint>

// ===========================================================================
// TreeModel via single-pass fp16 HMMA GEMMs (fp32 accumulate).
//   GEMM1: p = sigmoid(x @ W_gate + b)   A = fp16(x),     B = fp16(W^T)
//   tree : probs (path products)         -> fp16
//   GEMM2: out = probs @ leaf_logits     A = fp16(probs), B = fp16(leaf^T)
// ===========================================================================

#define M_DIM   16384
#define K_DIM   1024
#define N_GATE  1023
#define N_OUT   1000

#define BM      128
#define BN      128
#define BK      64          // 64 fp16 = 128B rows (swizzled)
#define NCHUNKS 16          // 1024 / 64
#define STAGES  3

#define A_BYTES (BM * BK * 2)        // 16 KB
#define B_BYTES (BN * BK * 2)        // 16 KB
#define STG_BYTES (A_BYTES + B_BYTES)
#define SMEM_TOTAL (STAGES * STG_BYTES)   // 96 KB

// ---- scratch (static device allocations) ----
__device__ float   g_p  [(size_t)M_DIM * 1024];   // gate probabilities (f32)
__device__ __half  g_xh [(size_t)M_DIM * 1024];   // fp16(x)
__device__ __half  g_ph [(size_t)M_DIM * 1024];   // fp16(probs)
__device__ __half  g_wh [1024 * 1024];            // W_gate^T fp16
__device__ __half  g_lh [1024 * 1024];            // leaf^T fp16

__device__ __forceinline__ uint32_t smem_u32(const void* p) {
    uint32_t a;
    asm("{ .reg .u64 t; cvta.to.shared.u64 t, %1; cvt.u32.u64 %0, t; }" : "=r"(a) : "l"(p));
    return a;
}
__device__ __forceinline__ void cp16(uint32_t saddr, const void* gaddr) {
    asm volatile("cp.async.cg.shared.global [%0], [%1], 16;" :: "r"(saddr), "l"(gaddr));
}
__device__ __forceinline__ void ldsm_x4(uint32_t& r0, uint32_t& r1, uint32_t& r2, uint32_t& r3,
                                        uint32_t addr) {
    asm volatile("ldmatrix.sync.aligned.m8n8.x4.shared.b16 {%0,%1,%2,%3}, [%4];"
                 : "=r"(r0), "=r"(r1), "=r"(r2), "=r"(r3) : "r"(addr));
}
__device__ __forceinline__ void mma16816(float* c, const uint32_t* a, uint32_t b0, uint32_t b1) {
    asm volatile("mma.sync.aligned.m16n8k16.row.col.f32.f16.f16.f32 "
                 "{%0,%1,%2,%3}, {%4,%5,%6,%7}, {%8,%9}, {%0,%1,%2,%3};"
                 : "+f"(c[0]), "+f"(c[1]), "+f"(c[2]), "+f"(c[3])
                 : "r"(a[0]), "r"(a[1]), "r"(a[2]), "r"(a[3]), "r"(b0), "r"(b1));
}

// load one 128x64 A tile + 128x64 B tile into stage `st` (swizzled)
__device__ __forceinline__ void load_tiles(
    uint32_t sbase, int st, int tid, int bm0, int bn0, int k0,
    const __half* __restrict__ A, const __half* __restrict__ B)
{
    const uint32_t sa = sbase + (uint32_t)st * STG_BYTES;
    const uint32_t sb = sa + A_BYTES;
    #pragma unroll
    for (int i = 0; i < 4; i++) {
        int idx = i * 256 + tid;                 // 0..1023
        int row = idx >> 3;                      // 0..127
        int ch  = idx & 7;                       // 16B chunk in row
        uint32_t col = (uint32_t)ch * 16;
        uint32_t sw  = (uint32_t)row * 128 + (col ^ (((uint32_t)row & 7u) << 4));
        cp16(sa + sw, A + (size_t)(bm0 + row) * K_DIM + k0 + ch * 8);
        cp16(sb + sw, B + (size_t)(bn0 + row) * K_DIM + k0 + ch * 8);
    }
    asm volatile("cp.async.commit_group;" ::: "memory");
}

// ---------------------------------------------------------------------------
// EPI=1: sigmoid(acc + bias) -> C (ldc=1024)
// EPI=0: acc -> C (ldc=N_OUT, guard col < N_OUT)
// ---------------------------------------------------------------------------
template<int EPI>
__global__ void __launch_bounds__(256, 2)
hmma_gemm(const __half* __restrict__ A, const __half* __restrict__ B,
          const float* __restrict__ bias, float* __restrict__ C)
{
    extern __shared__ char smem[];
    const uint32_t sbase = smem_u32(smem);
    const int tid  = threadIdx.x;
    const int lane = tid & 31;
    const int wid  = tid >> 5;
    const int wm   = wid >> 1;          // 0..3
    const int wn   = wid & 1;           // 0..1
    const int m0w  = wm * 32;
    const int n0w  = wn * 64;
    const int bm0  = blockIdx.y * BM;
    const int bn0  = blockIdx.x * BN;

    // ldmatrix addressing: addr = rowBase + ((lh*16 + ks*32) ^ swmask)
    const int lr = lane & 15;
    const int lh = lane >> 4;
    const uint32_t sw = ((uint32_t)lr & 7u) << 4;
    uint32_t colX[4];
    #pragma unroll
    for (int ks = 0; ks < 4; ks++)
        colX[ks] = (((uint32_t)lh * 16) + (uint32_t)ks * 32) ^ sw;
    uint32_t aRow[2], bRow[4];
    #pragma unroll
    for (int mt = 0; mt < 2; mt++) aRow[mt] = (uint32_t)(m0w + mt * 16 + lr) * 128;
    #pragma unroll
    for (int p = 0; p < 4; p++)    bRow[p]  = (uint32_t)(n0w + p * 16 + lr) * 128;

    float acc[2][8][4];
    #pragma unroll
    for (int mt = 0; mt < 2; mt++)
        #pragma unroll
        for (int nt = 0; nt < 8; nt++)
            #pragma unroll
            for (int q = 0; q < 4; q++) acc[mt][nt][q] = 0.f;

    load_tiles(sbase, 0, tid, bm0, bn0, 0, A, B);
    load_tiles(sbase, 1, tid, bm0, bn0, BK, A, B);

    for (int c = 0; c < NCHUNKS; c++) {
        if (c + 1 < NCHUNKS) asm volatile("cp.async.wait_group 1;" ::: "memory");
        else                 asm volatile("cp.async.wait_group 0;" ::: "memory");
        __syncthreads();   // stage c visible; compute of c-1 finished by all

        const int pc = c + 2;
        if (pc < NCHUNKS)
            load_tiles(sbase, pc % STAGES, tid, bm0, bn0, pc * BK, A, B);

        const uint32_t sa = sbase + (uint32_t)(c % STAGES) * STG_BYTES;
        const uint32_t sb = sa + A_BYTES;

        #pragma unroll
        for (int ks = 0; ks < 4; ks++) {
            uint32_t a[2][4];
            #pragma unroll
            for (int mt = 0; mt < 2; mt++)
                ldsm_x4(a[mt][0], a[mt][1], a[mt][2], a[mt][3], sa + aRow[mt] + colX[ks]);
            uint32_t b[8][2];
            #pragma unroll
            for (int p = 0; p < 4; p++) {
                uint32_t r0, r1, r2, r3;
                ldsm_x4(r0, r1, r2, r3, sb + bRow[p] + colX[ks]);
                b[p*2][0] = r0; b[p*2][1] = r2;
                b[p*2+1][0] = r1; b[p*2+1][1] = r3;
            }
            #pragma unroll
            for (int mt = 0; mt < 2; mt++)
                #pragma unroll
                for (int nt = 0; nt < 8; nt++)
                    mma16816(acc[mt][nt], a[mt], b[nt][0], b[nt][1]);
        }
    }

    // epilogue
    const int gq = lane >> 2;
    const int tq = lane & 3;
    #pragma unroll
    for (int mt = 0; mt < 2; mt++) {
        #pragma unroll
        for (int nt = 0; nt < 8; nt++) {
            const int col = bn0 + n0w + nt * 8 + tq * 2;
            const int r0  = bm0 + m0w + mt * 16 + gq;
            float v0 = acc[mt][nt][0], v1 = acc[mt][nt][1];
            float v2 = acc[mt][nt][2], v3 = acc[mt][nt][3];
            if (EPI == 1) {
                float b0 = (col     < N_GATE) ? bias[col]     : 0.f;
                float b1 = (col + 1 < N_GATE) ? bias[col + 1] : 0.f;
                v0 = 1.f / (1.f + __expf(-(v0 + b0)));
                v1 = 1.f / (1.f + __expf(-(v1 + b1)));
                v2 = 1.f / (1.f + __expf(-(v2 + b0)));
                v3 = 1.f / (1.f + __expf(-(v3 + b1)));
                *(float2*)(C + (size_t)r0 * 1024 + col)       = make_float2(v0, v1);
                *(float2*)(C + (size_t)(r0 + 8) * 1024 + col) = make_float2(v2, v3);
            } else {
                if (col + 1 < N_OUT) {
                    *(float2*)(C + (size_t)r0 * N_OUT + col)       = make_float2(v0, v1);
                    *(float2*)(C + (size_t)(r0 + 8) * N_OUT + col) = make_float2(v2, v3);
                } else if (col < N_OUT) {
                    C[(size_t)r0 * N_OUT + col]       = v0;
                    C[(size_t)(r0 + 8) * N_OUT + col] = v2;
                }
            }
        }
    }
}

// ---------------------------------------------------------------------------
// x: f32 -> fp16
// ---------------------------------------------------------------------------
__global__ void __launch_bounds__(256)
cvt_kernel(const float* __restrict__ in, __half* __restrict__ out, int n4)
{
    int i = blockIdx.x * 256 + threadIdx.x;
    if (i >= n4) return;
    float4 v = ((const float4*)in)[i];
    __half2* O = (__half2*)out;
    O[i*2]   = __floats2half2_rn(v.x, v.y);
    O[i*2+1] = __floats2half2_rn(v.z, v.w);
}

// ---------------------------------------------------------------------------
// transpose + convert: in[1024, Nin] f32 -> [1024(N, zero pad), 1024(K)] fp16
// ---------------------------------------------------------------------------
__global__ void __launch_bounds__(256)
transpose_cvt_kernel(const float* __restrict__ in, int Nin,
                     __half* __restrict__ outT)
{
    __shared__ float t[32][33];
    const int k0 = blockIdx.x * 32, n0 = blockIdx.y * 32;
    const int x = threadIdx.x & 31, y = threadIdx.x >> 5;
    #pragma unroll
    for (int i = 0; i < 32; i += 8) {
        int n = n0 + x;
        t[y + i][x] = (n < Nin) ? in[(size_t)(k0 + y + i) * Nin + n] : 0.f;
    }
    __syncthreads();
    #pragma unroll
    for (int i = 0; i < 32; i += 8) {
        int n = n0 + y + i, k = k0 + x;
        outT[(size_t)n * 1024 + k] = __float2half_rn(t[x][y + i]);
    }
}

// ---------------------------------------------------------------------------
// Tree path-product -> probs as fp16.
// ---------------------------------------------------------------------------
__global__ void __launch_bounds__(256)
tree_kernel()
{
    __shared__ float sp[2][1024];
    const int half = threadIdx.x >> 7;
    const int t    = threadIdx.x & 127;
    const int s    = blockIdx.x * 2 + half;

    const float* prow = g_p + (size_t)s * 1024;
    #pragma unroll
    for (int i = 0; i < 8; i++) {
        int idx = t + i * 128;
        if (idx < N_GATE) sp[half][idx] = prow[idx];
    }
    __syncthreads();

    const float* pr = sp[half];
    const int base = t * 8;

    float pref = 1.0f;
    #pragma unroll
    for (int k = 0; k < 7; k++) {
        int node = (1 << k) - 1 + (base >> (10 - k));
        int bit  = (base >> (9 - k)) & 1;
        float pv = pr[node];
        pref *= bit ? pv : (1.0f - pv);
    }
    float p7 = pr[127 + (base >> 3)];
    float p8[2];
    p8[0] = pr[255 + (base >> 2) + 0];
    p8[1] = pr[255 + (base >> 2) + 1];
    float p9[4];
    #pragma unroll
    for (int i = 0; i < 4; i++) p9[i] = pr[511 + (base >> 1) + i];

    __align__(16) __half H[8];
    #pragma unroll
    for (int j = 0; j < 8; j++) {
        int b2 = (j >> 2) & 1, b1 = (j >> 1) & 1, b0 = j & 1;
        float v = pref * (b2 ? p7 : (1.0f - p7));
        float q8 = p8[b2];
        v *= b1 ? q8 : (1.0f - q8);
        float q9 = p9[j >> 1];
        v *= b0 ? q9 : (1.0f - q9);
        H[j] = __float2half_rn(v);
    }
    *(uint4*)(g_ph + (size_t)s * 1024 + base) = *(uint4*)H;
}

// ---------------------------------------------------------------------------
extern "C" void kernel_launch(void* const* d_in, const int* in_sizes, int n_in,
                              void* d_out, int out_size)
{
    const float* x    = (const float*)d_in[0];
    const float* Wg   = (const float*)d_in[1];
    const float* bg   = (const float*)d_in[2];
    const float* leaf = (const float*)d_in[3];
    float* out = (float*)d_out;

    float *p_ptr;
    __half *xh, *ph, *wh, *lh;
    cudaGetSymbolAddress((void**)&p_ptr, g_p);
    cudaGetSymbolAddress((void**)&xh, g_xh);
    cudaGetSymbolAddress((void**)&ph, g_ph);
    cudaGetSymbolAddress((void**)&wh, g_wh);
    cudaGetSymbolAddress((void**)&lh, g_lh);

    cudaFuncSetAttribute(hmma_gemm<1>, cudaFuncAttributeMaxDynamicSharedMemorySize, SMEM_TOTAL);
    cudaFuncSetAttribute(hmma_gemm<0>, cudaFuncAttributeMaxDynamicSharedMemorySize, SMEM_TOTAL);

    // prep: convert x; transpose+convert weights
    {
        int n4 = (M_DIM * K_DIM) / 4;
        cvt_kernel<<<(n4 + 255) / 256, 256>>>(x, xh, n4);
        dim3 tg(32, 32);
        transpose_cvt_kernel<<<tg, 256>>>(Wg, N_GATE, wh);
        transpose_cvt_kernel<<<tg, 256>>>(leaf, N_OUT, lh);
    }

    // GEMM1 + sigmoid -> g_p
    {
        dim3 grid(1024 / BN, M_DIM / BM);   // (8, 128)
        hmma_gemm<1><<<grid, 256, SMEM_TOTAL>>>(xh, wh, bg, p_ptr);
    }

    // tree products -> probs fp16
    tree_kernel<<<M_DIM / 2, 256>>>();

    // GEMM2 -> out
    {
        dim3 grid(1024 / BN, M_DIM / BM);   // (8, 128)
        hmma_gemm<0><<<grid, 256, SMEM_TOTAL>>>(ph, lh, nullptr, out);
    }
}